// round 14
// baseline (speedup 1.0000x reference)
#include <cuda_runtime.h>
#include <cuda_fp16.h>
#include <cstdint>

#define BATCH 4
#define CCH 256
#define NSP 4096
#define DQK 32

// scale * log2(e): softmax computed in exp2 domain
#define QSCALE (0.17677669529663687f * 1.4426950408889634f)

// ---------------- scratch (device globals; no allocation allowed) ----------------
__device__ __half g_qb[2 * BATCH * NSP * DQK];            // [sb][n][d] (scaled)
__device__ __half g_kb[2 * BATCH * NSP * DQK];            // [sb][m][d]
__device__ __half g_vb[(size_t)2 * BATCH * CCH * NSP];    // [sb][c][m]
__device__ __half g_aoh[(size_t)2 * BATCH * NSP * CCH];   // attn out fp16 [bb][n][c]
__device__ __half g_wqkv[320 * 256];                      // fused QKV weights (q pre-scaled)
__device__ float  g_bqkv[320];
__device__ __half g_w1h[256 * 256];
__device__ __half g_w2h[256 * 256];
__device__ __half g_h[(size_t)2 * BATCH * CCH * NSP];     // pre-LN fp16 [bb][c][n]
__device__ double g_sums[8][2];

// ---------------- weight prep + zero stats ----------------
__global__ void prep_w_kernel(
    const float* __restrict__ Wq, const float* __restrict__ bq,
    const float* __restrict__ Wk, const float* __restrict__ bk,
    const float* __restrict__ Wv, const float* __restrict__ bv,
    const float* __restrict__ W1, const float* __restrict__ W2)
{
    int idx = blockIdx.x * 256 + threadIdx.x;
    if (idx < 16) ((double*)g_sums)[idx] = 0.0;
    if (idx < 320) {
        float bv_;
        if (idx < 32)       bv_ = bq[idx] * QSCALE;
        else if (idx < 64)  bv_ = bk[idx - 32];
        else                bv_ = bv[idx - 64];
        g_bqkv[idx] = bv_;
    }
    if (idx < 81920) {
        int o = idx >> 8, c = idx & 255;
        float w;
        if (o < 32)       w = Wq[o * 256 + c] * QSCALE;
        else if (o < 64)  w = Wk[(o - 32) * 256 + c];
        else              w = Wv[(o - 64) * 256 + c];
        g_wqkv[idx] = __float2half(w);
    } else if (idx < 81920 + 65536) {
        int j = idx - 81920;
        g_w1h[j] = __float2half(W1[j]);
    } else if (idx < 81920 + 131072) {
        int j = idx - 81920 - 65536;
        g_w2h[j] = __float2half(W2[j]);
    }
}

// ---------------- common mma helpers ----------------
__device__ __forceinline__ void ldsm_x4(uint32_t& r0, uint32_t& r1, uint32_t& r2, uint32_t& r3,
                                        uint32_t addr) {
    asm volatile("ldmatrix.sync.aligned.m8n8.x4.shared.b16 {%0,%1,%2,%3}, [%4];\n"
                 : "=r"(r0), "=r"(r1), "=r"(r2), "=r"(r3) : "r"(addr));
}
__device__ __forceinline__ void ldsm_x4_t(uint32_t& r0, uint32_t& r1, uint32_t& r2, uint32_t& r3,
                                          uint32_t addr) {
    asm volatile("ldmatrix.sync.aligned.m8n8.x4.trans.shared.b16 {%0,%1,%2,%3}, [%4];\n"
                 : "=r"(r0), "=r"(r1), "=r"(r2), "=r"(r3) : "r"(addr));
}
__device__ __forceinline__ void mma_f16(float* d, const uint32_t* a, uint32_t b0, uint32_t b1) {
    asm volatile(
        "mma.sync.aligned.m16n8k16.row.col.f32.f16.f16.f32 "
        "{%0,%1,%2,%3},{%4,%5,%6,%7},{%8,%9},{%0,%1,%2,%3};\n"
        : "+f"(d[0]), "+f"(d[1]), "+f"(d[2]), "+f"(d[3])
        : "r"(a[0]), "r"(a[1]), "r"(a[2]), "r"(a[3]), "r"(b0), "r"(b1));
}
__device__ __forceinline__ float ex2(float x) {
    float r;
    asm("ex2.approx.f32 %0, %1;" : "=f"(r) : "f"(x));
    return r;
}
__device__ __forceinline__ void cp16(uint32_t dst, const void* src) {
    asm volatile("cp.async.cg.shared.global [%0], [%1], 16;\n" :: "r"(dst), "l"(src));
}

// ---------------- QKV projection: x resident, o-tiles looped in-CTA ----------------
// grid (64 n-tiles of 64, 8 sb), 256 thr, 2 CTAs/SM.
#define PROJ_XSTR 72
#define PROJ_WSTR 264
#define PROJ_SMEM (256 * PROJ_XSTR * 2 + 64 * PROJ_WSTR * 2)
__global__ __launch_bounds__(256, 2) void proj_kernel(
    const float* __restrict__ x, const float* __restrict__ y)
{
    extern __shared__ __align__(16) char smem_raw[];
    __half* x_s = (__half*)smem_raw;                 // [256 c][72 n]
    __half* w_s = x_s + 256 * PROJ_XSTR;             // [64 o][264]; staging [64][72] on last ot

    const int tid = threadIdx.x;
    const int lane = tid & 31;
    const int warp = tid >> 5;
    const int wm = warp >> 2;        // 0..1 -> o range 32
    const int wn = warp & 3;         // 0..3 -> n range 16
    const int n0 = blockIdx.x * 64;
    const int sb = blockIdx.y;

    const uint32_t s_x = (uint32_t)__cvta_generic_to_shared(x_s);
    const uint32_t s_w = (uint32_t)__cvta_generic_to_shared(w_s);

    // load x tile [256 c][64 n] fp32 -> fp16 (4 threads per c-row, 16 floats each)
    const float* in = (sb < 4 ? x : y) + (size_t)(sb & 3) * CCH * NSP;
#pragma unroll
    for (int i = 0; i < 4; i++) {
        int c = (tid >> 2) + i * 64;
        int nseg = (tid & 3) * 16;
        const float* src = in + (size_t)c * NSP + n0 + nseg;
        __half* dst = x_s + c * PROJ_XSTR + nseg;
#pragma unroll
        for (int q = 0; q < 4; q++) {
            float4 v = *(const float4*)&src[q * 4];
            *(__half2*)&dst[q * 4]     = __floats2half2_rn(v.x, v.y);
            *(__half2*)&dst[q * 4 + 2] = __floats2half2_rn(v.z, v.w);
        }
    }
    __syncthreads();

    const int rloc = lane >> 2;
    const int cloc = 2 * (lane & 3);

#pragma unroll
    for (int ott = 0; ott < 5; ott++) {
        const int ot = (ott + 1) % 5;      // order 1,2,3,4,0 (q/k last: stage reuses w_s)
        const int o0 = ot * 64;

        if (ott > 0) __syncthreads();       // prior mma reads of w_s complete
        // load W tile [64][256]
#pragma unroll
        for (int i = 0; i < 8; i++) {
            int idx = tid + i * 256;
            int row = idx >> 5, col8 = (idx & 31) * 8;
            *(int4*)&w_s[row * PROJ_WSTR + col8] = *(const int4*)&g_wqkv[(o0 + row) * 256 + col8];
        }
        __syncthreads();

        float acc[2][2][4];
#pragma unroll
        for (int i = 0; i < 2; i++)
#pragma unroll
            for (int j = 0; j < 2; j++)
#pragma unroll
                for (int v = 0; v < 4; v++) acc[i][j][v] = 0.f;

#pragma unroll
        for (int k = 0; k < 16; k++) {
            uint32_t af[2][4];
#pragma unroll
            for (int i = 0; i < 2; i++)
                ldsm_x4(af[i][0], af[i][1], af[i][2], af[i][3],
                        s_w + ((wm * 32 + i * 16 + (lane & 15)) * PROJ_WSTR + k * 16 + (lane >> 4) * 8) * 2);
            uint32_t r0, r1, r2, r3;
            ldsm_x4_t(r0, r1, r2, r3,
                      s_x + ((k * 16 + (lane & 15)) * PROJ_XSTR + wn * 16 + (lane >> 4) * 8) * 2);
#pragma unroll
            for (int i = 0; i < 2; i++) {
                mma_f16(acc[i][0], af[i], r0, r1);
                mma_f16(acc[i][1], af[i], r2, r3);
            }
        }

        if (ot != 0) {
            // v rows: direct [c][m] writes
            __half* vp = g_vb + (size_t)sb * CCH * NSP;
#pragma unroll
            for (int i = 0; i < 2; i++) {
                int orow = o0 - 64 + wm * 32 + i * 16 + rloc;
                float b0 = g_bqkv[o0 + wm * 32 + i * 16 + rloc];
                float b1 = g_bqkv[o0 + wm * 32 + i * 16 + rloc + 8];
#pragma unroll
                for (int j = 0; j < 2; j++) {
                    int c = n0 + wn * 16 + j * 8 + cloc;
                    *(__half2*)&vp[(size_t)orow * NSP + c] =
                        __floats2half2_rn(acc[i][j][0] + b0, acc[i][j][1] + b0);
                    *(__half2*)&vp[(size_t)(orow + 8) * NSP + c] =
                        __floats2half2_rn(acc[i][j][2] + b1, acc[i][j][3] + b1);
                }
            }
        } else {
            // q (rows 0-31) / k (rows 32-63): stage [64 o][72 n] in w_s, transposed writes
            __half* stage = w_s;
            __syncthreads();   // all mma reads of w_s done before overwrite
#pragma unroll
            for (int i = 0; i < 2; i++) {
                int orow = wm * 32 + i * 16 + rloc;
                float b0 = g_bqkv[orow], b1 = g_bqkv[orow + 8];
#pragma unroll
                for (int j = 0; j < 2; j++) {
                    int nl = wn * 16 + j * 8 + cloc;
                    *(__half2*)&stage[orow * 72 + nl] =
                        __floats2half2_rn(acc[i][j][0] + b0, acc[i][j][1] + b0);
                    *(__half2*)&stage[(orow + 8) * 72 + nl] =
                        __floats2half2_rn(acc[i][j][2] + b1, acc[i][j][3] + b1);
                }
            }
            __syncthreads();
            // q: [n][32] from rows 0-31 ; k: [m][32] from rows 32-63 (2048 half2 ops)
#pragma unroll
            for (int i = 0; i < 8; i++) {
                int idx = tid + i * 256;
                int which = idx >> 10;          // 0 = q, 1 = k
                int sub = idx & 1023;
                int n = sub >> 4, d2 = sub & 15;
                __half h0 = stage[(which * 32 + 2 * d2) * 72 + n];
                __half h1 = stage[(which * 32 + 2 * d2 + 1) * 72 + n];
                __half* dst = which == 0 ? g_qb : g_kb;
                *(__half2*)&dst[((size_t)sb * NSP + n0 + n) * DQK + 2 * d2] = __halves2half2(h0, h1);
            }
        }
    }
}

// ---------------- flash attention: Br=128, fixed-max softmax, cp.async pipeline ----------------
#define TSTR 72
#define AK_HALFS (64 * TSTR)
#define AV_HALFS (256 * TSTR)
#define AP_HALFS (128 * TSTR)
#define ATTN_SMEM ((2 * AK_HALFS + 2 * AV_HALFS + 2 * AP_HALFS) * 2 + 1024)

__global__ __launch_bounds__(512, 1) void attn_kernel()
{
    extern __shared__ __align__(16) char smem_raw[];
    __half* k_s = (__half*)smem_raw;            // [2][64][72]
    __half* v_s = k_s + 2 * AK_HALFS;           // [2][256][72]
    __half* p_s = v_s + 2 * AV_HALFS;           // [2][128][72]
    float* red  = (float*)(p_s + 2 * AP_HALFS); // [128][2]

    const int tid = threadIdx.x;
    const int lane = tid & 31;
    const int warp = tid >> 5;
    const int rg = warp >> 1;
    const int cs = warp & 1;
    const int rowbase = rg * 16;
    const int br = blockIdx.z, b = blockIdx.y;
    const int q0 = blockIdx.x * 128;
    const int bb = br * 4 + b;
    const int kb = (1 - br) * 4 + b;

    const uint32_t s_k = (uint32_t)__cvta_generic_to_shared(k_s);
    const uint32_t s_v = (uint32_t)__cvta_generic_to_shared(v_s);
    const uint32_t s_p = (uint32_t)__cvta_generic_to_shared(p_s);

    const __half* kg = g_kb + (size_t)kb * NSP * DQK;
    const __half* vg = g_vb + (size_t)kb * CCH * NSP;

    const int rA = rowbase + (lane >> 2);
    const int rB = rA + 8;

    uint32_t qa[2][4];
    {
        const __half* qp = g_qb + ((size_t)bb * NSP + q0) * DQK;
        int c0 = (lane & 3) * 2;
#pragma unroll
        for (int ks = 0; ks < 2; ks++) {
            qa[ks][0] = *(const uint32_t*)&qp[(size_t)rA * 32 + ks * 16 + c0];
            qa[ks][1] = *(const uint32_t*)&qp[(size_t)rB * 32 + ks * 16 + c0];
            qa[ks][2] = *(const uint32_t*)&qp[(size_t)rA * 32 + ks * 16 + c0 + 8];
            qa[ks][3] = *(const uint32_t*)&qp[(size_t)rB * 32 + ks * 16 + c0 + 8];
        }
    }

    float o[16][4];
#pragma unroll
    for (int i = 0; i < 16; i++)
#pragma unroll
        for (int j = 0; j < 4; j++) o[i][j] = 0.f;
    float lA = 0.f, lB = 0.f;

    {
        if (tid < 256) {
            int key = tid >> 2, part = tid & 3;
            cp16(s_k + (key * TSTR + part * 8) * 2, kg + (size_t)key * DQK + part * 8);
        }
#pragma unroll
        for (int j = 0; j < 4; j++) {
            int idx = tid + j * 512;
            int c = idx >> 3, part = idx & 7;
            cp16(s_v + (c * TSTR + part * 8) * 2, vg + (size_t)c * NSP + part * 8);
        }
        asm volatile("cp.async.commit_group;\n");
    }

    for (int it = 0; it < 64; it++) {
        const int bf = it & 1;
        const int t0 = it * 64;
        asm volatile("cp.async.wait_group 0;\n");
        __syncthreads();

        {
            int tn = (t0 + 64) & (NSP - 1);
            uint32_t kd = s_k + (1 - bf) * AK_HALFS * 2;
            uint32_t vd = s_v + (1 - bf) * AV_HALFS * 2;
            if (tid < 256) {
                int key = tid >> 2, part = tid & 3;
                cp16(kd + (key * TSTR + part * 8) * 2, kg + (size_t)(tn + key) * DQK + part * 8);
            }
#pragma unroll
            for (int j = 0; j < 4; j++) {
                int idx = tid + j * 512;
                int c = idx >> 3, part = idx & 7;
                cp16(vd + (c * TSTR + part * 8) * 2, vg + (size_t)c * NSP + tn + part * 8);
            }
            asm volatile("cp.async.commit_group;\n");
        }

        const uint32_t kbase = s_k + bf * AK_HALFS * 2;
        float s[4][4];
#pragma unroll
        for (int i = 0; i < 4; i++)
#pragma unroll
            for (int j = 0; j < 4; j++) s[i][j] = 0.f;
#pragma unroll
        for (int ks = 0; ks < 2; ks++) {
#pragma unroll
            for (int nt16 = 0; nt16 < 2; nt16++) {
                uint32_t r0, r1, r2, r3;
                uint32_t addr = kbase +
                    ((cs * 32 + nt16 * 16 + (lane & 15)) * TSTR + ks * 16 + (lane >> 4) * 8) * 2;
                ldsm_x4(r0, r1, r2, r3, addr);
                mma_f16(s[nt16 * 2 + 0], qa[ks], r0, r2);
                mma_f16(s[nt16 * 2 + 1], qa[ks], r1, r3);
            }
        }

        __half* pw = p_s + bf * AP_HALFS;
#pragma unroll
        for (int nt = 0; nt < 4; nt++) {
            float p0 = ex2(s[nt][0]), p1 = ex2(s[nt][1]);
            float p2 = ex2(s[nt][2]), p3 = ex2(s[nt][3]);
            lA += p0 + p1; lB += p2 + p3;
            int col = cs * 32 + nt * 8 + (lane & 3) * 2;
            *(__half2*)&pw[rA * TSTR + col] = __float22half2_rn(make_float2(p0, p1));
            *(__half2*)&pw[rB * TSTR + col] = __float22half2_rn(make_float2(p2, p3));
        }
        __syncthreads();

        const uint32_t pbase = s_p + bf * AP_HALFS * 2;
        const uint32_t vbase = s_v + bf * AV_HALFS * 2;
#pragma unroll
        for (int ks = 0; ks < 4; ks++) {
            uint32_t pa[4];
            uint32_t paddr = pbase +
                ((rowbase + (lane & 15)) * TSTR + ks * 16 + (lane >> 4) * 8) * 2;
            ldsm_x4(pa[0], pa[1], pa[2], pa[3], paddr);
#pragma unroll
            for (int ct = 0; ct < 8; ct++) {
                uint32_t r0, r1, r2, r3;
                uint32_t vaddr = vbase +
                    ((cs * 128 + ct * 16 + (lane & 15)) * TSTR + ks * 16 + (lane >> 4) * 8) * 2;
                ldsm_x4(r0, r1, r2, r3, vaddr);
                mma_f16(o[ct * 2 + 0], pa, r0, r2);
                mma_f16(o[ct * 2 + 1], pa, r1, r3);
            }
        }
    }

    lA += __shfl_xor_sync(0xffffffffu, lA, 1);
    lA += __shfl_xor_sync(0xffffffffu, lA, 2);
    lB += __shfl_xor_sync(0xffffffffu, lB, 1);
    lB += __shfl_xor_sync(0xffffffffu, lB, 2);
    if ((lane & 3) == 0) {
        red[rA * 2 + cs] = lA;
        red[rB * 2 + cs] = lB;
    }
    __syncthreads();
    float ivA = 1.f / (red[rA * 2] + red[rA * 2 + 1]);
    float ivB = 1.f / (red[rB * 2] + red[rB * 2 + 1]);

    __half* op = g_aoh + ((size_t)bb * NSP + q0) * CCH;
#pragma unroll
    for (int nt = 0; nt < 16; nt++) {
        int col = cs * 128 + nt * 8 + (lane & 3) * 2;
        *(__half2*)&op[(size_t)rA * CCH + col] =
            __floats2half2_rn(o[nt][0] * ivA, o[nt][1] * ivA);
        *(__half2*)&op[(size_t)rB * CCH + col] =
            __floats2half2_rn(o[nt][2] * ivB, o[nt][3] * ivB);
    }
}

// ---------------- MLP (depth-3 cp.async weight pipeline) + LN stats, fp16 h ----------------
#define MLP_ASTR 264
#define MLP_HSTR 72
#define MLP_WSTR 24
#define MLP_SMEM (64 * MLP_ASTR * 2 + 256 * MLP_HSTR * 2 + 3 * 256 * MLP_WSTR * 2 + 2048)
__global__ __launch_bounds__(256, 2) void mlp_kernel(
    const float* __restrict__ b1, const float* __restrict__ b2)
{
    extern __shared__ __align__(16) char smem_raw[];
    __half* a_s  = (__half*)smem_raw;
    __half* h1_s = a_s + 64 * MLP_ASTR;
    __half* w_s  = h1_s + 256 * MLP_HSTR;        // [3][256][24]
    float* red   = (float*)(w_s + 3 * 256 * MLP_WSTR);

    const int tid = threadIdx.x;
    const int lane = tid & 31;
    const int warp = tid >> 5;
    const int n0 = blockIdx.x * 64;
    const int bb = blockIdx.y;

    const uint32_t s_a = (uint32_t)__cvta_generic_to_shared(a_s);
    const uint32_t s_h = (uint32_t)__cvta_generic_to_shared(h1_s);
    const uint32_t s_w = (uint32_t)__cvta_generic_to_shared(w_s);

    auto issue_w = [&](const __half* wsrc, int k, int buf) {
#pragma unroll
        for (int i = 0; i < 2; i++) {
            int idx = tid + i * 256;
            int row = idx >> 1, col8 = (idx & 1) * 8;
            cp16(s_w + ((buf * 256 + row) * MLP_WSTR + col8) * 2,
                 wsrc + row * 256 + k * 16 + col8);
        }
        asm volatile("cp.async.commit_group;\n");
    };

    const __half* ip = g_aoh + (size_t)bb * NSP * CCH;
#pragma unroll
    for (int i = 0; i < 8; i++) {
        int idx = tid + i * 256;
        int row = idx >> 5, col8 = (idx & 31) * 8;
        cp16(s_a + (row * MLP_ASTR + col8) * 2, ip + (size_t)(n0 + row) * CCH + col8);
    }
    asm volatile("cp.async.commit_group;\n");
    issue_w(g_w1h, 0, 0);
    issue_w(g_w1h, 1, 1);

    const int rloc = lane >> 2;
    const int cloc = 2 * (lane & 3);

    float acc[2][8][4];
#pragma unroll
    for (int i = 0; i < 2; i++)
#pragma unroll
        for (int j = 0; j < 8; j++)
#pragma unroll
            for (int v = 0; v < 4; v++) acc[i][j][v] = 0.f;

#pragma unroll
    for (int k = 0; k < 16; k++) {
        asm volatile("cp.async.wait_group 1;\n");
        __syncthreads();
        if (k < 14)      issue_w(g_w1h, k + 2, (k + 2) % 3);
        else if (k == 14) issue_w(g_w2h, 0, 16 % 3);
        else              issue_w(g_w2h, 1, 17 % 3);
        int buf = k % 3;
        uint32_t af[2][4];
#pragma unroll
        for (int i = 0; i < 2; i++)
            ldsm_x4(af[i][0], af[i][1], af[i][2], af[i][3],
                    s_w + ((buf * 256 + warp * 32 + i * 16 + (lane & 15)) * MLP_WSTR + (lane >> 4) * 8) * 2);
#pragma unroll
        for (int nf = 0; nf < 4; nf++) {
            uint32_t r0, r1, r2, r3;
            ldsm_x4(r0, r1, r2, r3,
                    s_a + ((nf * 16 + (lane & 15)) * MLP_ASTR + k * 16 + (lane >> 4) * 8) * 2);
#pragma unroll
            for (int i = 0; i < 2; i++) {
                mma_f16(acc[i][nf * 2 + 0], af[i], r0, r2);
                mma_f16(acc[i][nf * 2 + 1], af[i], r1, r3);
            }
        }
    }

#pragma unroll
    for (int i = 0; i < 2; i++) {
        int oA = warp * 32 + i * 16 + rloc;
        float bA = b1[oA], bB = b1[oA + 8];
#pragma unroll
        for (int j = 0; j < 8; j++) {
            int c = j * 8 + cloc;
            *(__half2*)&h1_s[oA * MLP_HSTR + c] =
                __floats2half2_rn(fmaxf(acc[i][j][0] + bA, 0.f), fmaxf(acc[i][j][1] + bA, 0.f));
            *(__half2*)&h1_s[(oA + 8) * MLP_HSTR + c] =
                __floats2half2_rn(fmaxf(acc[i][j][2] + bB, 0.f), fmaxf(acc[i][j][3] + bB, 0.f));
        }
    }

#pragma unroll
    for (int i = 0; i < 2; i++)
#pragma unroll
        for (int j = 0; j < 8; j++)
#pragma unroll
            for (int v = 0; v < 4; v++) acc[i][j][v] = 0.f;

#pragma unroll
    for (int j2 = 0; j2 < 16; j2++) {
        if (j2 < 15) asm volatile("cp.async.wait_group 1;\n");
        else         asm volatile("cp.async.wait_group 0;\n");
        __syncthreads();
        if (j2 < 14) issue_w(g_w2h, j2 + 2, (j2 + 3) % 3);
        int buf = (j2 + 1) % 3;
        uint32_t af[2][4];
#pragma unroll
        for (int i = 0; i < 2; i++)
            ldsm_x4(af[i][0], af[i][1], af[i][2], af[i][3],
                    s_w + ((buf * 256 + warp * 32 + i * 16 + (lane & 15)) * MLP_WSTR + (lane >> 4) * 8) * 2);
#pragma unroll
        for (int nf = 0; nf < 4; nf++) {
            uint32_t r0, r1, r2, r3;
            ldsm_x4_t(r0, r1, r2, r3,
                      s_h + ((j2 * 16 + (lane & 15)) * MLP_HSTR + nf * 16 + (lane >> 4) * 8) * 2);
#pragma unroll
            for (int i = 0; i < 2; i++) {
                mma_f16(acc[i][nf * 2 + 0], af[i], r0, r1);
                mma_f16(acc[i][nf * 2 + 1], af[i], r2, r3);
            }
        }
    }

    float lsum = 0.f, lss = 0.f;
    __half* hp = g_h + (size_t)bb * CCH * NSP;
#pragma unroll
    for (int i = 0; i < 2; i++) {
        int oA = warp * 32 + i * 16 + rloc;
        float bA = b2[oA], bB = b2[oA + 8];
#pragma unroll
        for (int j = 0; j < 8; j++) {
            int c = n0 + j * 8 + cloc;
            float v0 = acc[i][j][0] + bA, v1 = acc[i][j][1] + bA;
            float v2 = acc[i][j][2] + bB, v3 = acc[i][j][3] + bB;
            *(__half2*)&hp[(size_t)oA * NSP + c] = __floats2half2_rn(v0, v1);
            *(__half2*)&hp[(size_t)(oA + 8) * NSP + c] = __floats2half2_rn(v2, v3);
            lsum += v0 + v1 + v2 + v3;
            lss += v0 * v0 + v1 * v1 + v2 * v2 + v3 * v3;
        }
    }
    __syncthreads();
    red[tid] = lsum;
    red[256 + tid] = lss;
    __syncthreads();
    for (int st = 128; st > 0; st >>= 1) {
        if (tid < st) { red[tid] += red[tid + st]; red[256 + tid] += red[256 + tid + st]; }
        __syncthreads();
    }
    if (tid == 0) {
        atomicAdd(&g_sums[bb][0], (double)red[0]);
        atomicAdd(&g_sums[bb][1], (double)red[256]);
    }
}

// ---------------- LayerNorm apply (fp16 h input) ----------------
__global__ void ln_kernel(const float* __restrict__ gamma, const float* __restrict__ beta,
                          float* __restrict__ out)
{
    int idx4 = blockIdx.x * blockDim.x + threadIdx.x;
    int base = idx4 * 4;
    int bb = base >> 20;
    int cn = base & ((1 << 20) - 1);
    const double invM = 1.0 / 1048576.0;
    double mu = g_sums[bb][0] * invM;
    double var = g_sums[bb][1] * invM - mu * mu;
    float rstd = rsqrtf((float)var + 1e-5f);
    float muf = (float)mu;
    __half2 h01 = *(const __half2*)&g_h[(size_t)base];
    __half2 h23 = *(const __half2*)&g_h[(size_t)base + 2];
    float2 f01 = __half22float2(h01);
    float2 f23 = __half22float2(h23);
    float4 g4 = *(const float4*)&gamma[cn];
    float4 be4 = *(const float4*)&beta[cn];
    float4 o4;
    o4.x = (f01.x - muf) * rstd * g4.x + be4.x;
    o4.y = (f01.y - muf) * rstd * g4.y + be4.y;
    o4.z = (f23.x - muf) * rstd * g4.z + be4.z;
    o4.w = (f23.y - muf) * rstd * g4.w + be4.w;
    *(float4*)&out[base] = o4;
}

// ---------------- launch ----------------
extern "C" void kernel_launch(void* const* d_in, const int* in_sizes, int n_in,
                              void* d_out, int out_size)
{
    const float* x     = (const float*)d_in[0];
    const float* y     = (const float*)d_in[1];
    const float* Wq    = (const float*)d_in[2];
    const float* bq    = (const float*)d_in[3];
    const float* Wk    = (const float*)d_in[4];
    const float* bk    = (const float*)d_in[5];
    const float* Wv    = (const float*)d_in[6];
    const float* bv    = (const float*)d_in[7];
    const float* W1    = (const float*)d_in[8];
    const float* b1    = (const float*)d_in[9];
    const float* W2    = (const float*)d_in[10];
    const float* b2    = (const float*)d_in[11];
    const float* gamma = (const float*)d_in[12];
    const float* beta  = (const float*)d_in[13];
    float* out = (float*)d_out;

    cudaFuncSetAttribute(attn_kernel, cudaFuncAttributeMaxDynamicSharedMemorySize, ATTN_SMEM);
    cudaFuncSetAttribute(proj_kernel, cudaFuncAttributeMaxDynamicSharedMemorySize, PROJ_SMEM);
    cudaFuncSetAttribute(mlp_kernel,  cudaFuncAttributeMaxDynamicSharedMemorySize, MLP_SMEM);

    prep_w_kernel<<<832, 256>>>(Wq, bq, Wk, bk, Wv, bv, W1, W2);
    proj_kernel<<<dim3(64, 8), 256, PROJ_SMEM>>>(x, y);
    attn_kernel<<<dim3(32, 4, 2), 512, ATTN_SMEM>>>();
    mlp_kernel<<<dim3(64, 8), 256, MLP_SMEM>>>(b1, b2);
    ln_kernel<<<8192, 256>>>(gamma, beta, out);
}